// round 16
// baseline (speedup 1.0000x reference)
#include <cuda_runtime.h>
#include <math.h>

#define DIM   1024
#define NC    8
#define NPER  4096
#define QDIM  128
#define TOPK  128
#define HBITS 12
#define HBINS (1 << HBITS)      // 4096 bins per cluster
#define CANDMAX 640

// Scratch (no allocations allowed -> __device__ globals)
__device__ float g_w[NC][DIM];                   // q_w^T @ qk per cluster
__device__ float g_b0[NC];                       // q_b . qk
__device__ unsigned long long g_keys[NC][NPER];  // (desc-map(score)<<32)|idx
__device__ unsigned g_hist[NC][HBINS];           // 12-bit key-prefix histogram
__device__ int   g_topidx[NC][TOPK];             // sorted top-k indices
__device__ float g_gvec[NC][DIM];                // sum_n e^{s_n} feats[n]
__device__ float g_Z[NC];                        // sum_n e^{s_n}
__device__ unsigned g_flag[NC];                  // topidx-ready flags

// ---------------------------------------------------------------------------
// Kernel A (PARALLELIZED 8x): grid = NC*8, block = 256.
// Block (c, j): computes full qk (redundantly, key cached in registers,
// q_w from L2), then w[c][j*128 .. j*128+127] with the q-sum split across
// two thread halves. Zeroing sliced across the 8 blocks; b0 by block j==0.
// ---------------------------------------------------------------------------
__global__ __launch_bounds__(256) void prep_kernel(const float* __restrict__ key_feats,
                                                   const float* __restrict__ q_w,
                                                   const float* __restrict__ q_b) {
    __shared__ __align__(16) float s_qk[QDIM];
    __shared__ float wred[128];
    __shared__ float bred[4];
    int bid = blockIdx.x;
    int c = bid >> 3, j = bid & 7;
    int t = threadIdx.x, warp = t >> 5, lane = t & 31;

    // zero slices (hist: 1024 uint4 per cluster -> 128 per block)
    if (t < 128) {
        ((uint4*)g_hist[c])[j * 128 + t] = make_uint4(0u, 0u, 0u, 0u);
        g_gvec[c][j * 128 + t] = 0.f;
    }
    if (j == 0 && t == 0) { g_Z[c] = 0.f; g_flag[c] = 0u; }

    // cache key row in registers: 8 float4/lane = full 1024 across the warp
    const float4* kr = (const float4*)(key_feats + (size_t)c * DIM);
    float4 kreg[8];
    #pragma unroll
    for (int k = 0; k < 8; k++) kreg[k] = kr[lane + k * 32];

    // qk: warp handles rows [warp*16, warp*16+16)
    for (int r = 0; r < 16; r++) {
        int q = warp * 16 + r;
        const float4* qr = (const float4*)(q_w + (size_t)q * DIM);
        float a = 0.f;
        #pragma unroll
        for (int k = 0; k < 8; k++) {
            float4 x = qr[lane + k * 32];
            a += x.x * kreg[k].x + x.y * kreg[k].y
               + x.z * kreg[k].z + x.w * kreg[k].w;
        }
        #pragma unroll
        for (int o = 16; o > 0; o >>= 1)
            a += __shfl_xor_sync(0xffffffffu, a, o);
        if (lane == 0) s_qk[q] = a + q_b[q];
    }
    __syncthreads();

    // w slice: col = j*128 + (t&127); q-range half chosen by t>>7
    int col = j * 128 + (t & 127);
    int q0 = (t >> 7) * 64;
    float wacc = 0.f;
    #pragma unroll 16
    for (int q = 0; q < 64; q++)
        wacc += s_qk[q0 + q] * q_w[(size_t)(q0 + q) * DIM + col];
    if (t >= 128) wred[t - 128] = wacc;
    __syncthreads();
    if (t < 128) g_w[c][col] = wacc + wred[t];

    // b0 = qk . q_b (block j==0 only; uniform per block)
    if (j == 0) {
        float p = 0.f;
        if (t < QDIM) p = s_qk[t] * q_b[t];
        if (t < QDIM) {
            #pragma unroll
            for (int o = 16; o > 0; o >>= 1)
                p += __shfl_xor_sync(0xffffffffu, p, o);
            if (lane == 0) bred[warp] = p;
        }
        __syncthreads();
        if (t == 0) g_b0[c] = bred[0] + bred[1] + bred[2] + bred[3];
    }
}

// ---------------------------------------------------------------------------
// Kernel B: single-wave fused pass (R15-validated). UNCHANGED.
// 256 blocks x 128 rows, warp owns 16 rows, 8 float4/lane per row.
// ---------------------------------------------------------------------------
__global__ __launch_bounds__(256) void fused_pass_kernel(const float* __restrict__ feats) {
    __shared__ __align__(16) float sw[DIM];
    __shared__ __align__(16) float sacc[DIM];
    __shared__ float zsh;

    int bid = blockIdx.x;
    int c = bid >> 5;                    // 32 blocks per cluster
    int base = (bid & 31) * 128;
    int t = threadIdx.x, warp = t >> 5, lane = t & 31;

    ((float4*)sw)[t] = ((const float4*)(g_w[c]))[t];
    ((float4*)sacc)[t] = make_float4(0.f, 0.f, 0.f, 0.f);
    if (t == 0) zsh = 0.f;
    float b0 = g_b0[c];
    __syncthreads();

    const float4* fb =
        (const float4*)(feats + ((size_t)c * NPER + base + (size_t)warp * 16) * DIM);

    float4 acc[8];
    #pragma unroll
    for (int k = 0; k < 8; k++) acc[k] = make_float4(0.f, 0.f, 0.f, 0.f);
    float zw = 0.f;

    for (int r = 0; r < 16; r++) {
        float4 f[8];
        #pragma unroll
        for (int k = 0; k < 8; k++)
            f[k] = fb[(size_t)r * 256 + lane + k * 32];

        float d = 0.f;
        #pragma unroll
        for (int k = 0; k < 8; k++) {
            float4 w4 = ((const float4*)sw)[lane + k * 32];
            d += f[k].x * w4.x + f[k].y * w4.y + f[k].z * w4.z + f[k].w * w4.w;
        }
        #pragma unroll
        for (int o = 16; o > 0; o >>= 1)
            d += __shfl_xor_sync(0xffffffffu, d, o);

        float s = (d + b0) * 0.08838834764831845f;  // 1/sqrt(128)
        float e = expf(s);                           // |s| small: safe
        zw += e;

        if (lane == 0) {
            int n = base + warp * 16 + r;
            unsigned u = __float_as_uint(s);
            u = (u & 0x80000000u) ? ~u : (u | 0x80000000u);  // ascending map
            unsigned dm = ~u;                                // descending map
            g_keys[c][n] = ((unsigned long long)dm << 32) | (unsigned)n;
            atomicAdd(&g_hist[c][dm >> (32 - HBITS)], 1u);   // spread bins
        }

        #pragma unroll
        for (int k = 0; k < 8; k++) {
            acc[k].x += e * f[k].x; acc[k].y += e * f[k].y;
            acc[k].z += e * f[k].z; acc[k].w += e * f[k].w;
        }
    }

    // cross-warp combine (serialized rounds)
    for (int wi = 0; wi < 8; wi++) {
        if (warp == wi) {
            #pragma unroll
            for (int k = 0; k < 8; k++) {
                float4* p = &((float4*)sacc)[lane + k * 32];
                float4 v = *p;
                v.x += acc[k].x; v.y += acc[k].y;
                v.z += acc[k].z; v.w += acc[k].w;
                *p = v;
            }
            if (lane == 0) zsh += zw;
        }
        __syncthreads();
    }

    float4 v = ((float4*)sacc)[t];
    float* gp = g_gvec[c] + t * 4;
    atomicAdd(gp + 0, v.x);
    atomicAdd(gp + 1, v.y);
    atomicAdd(gp + 2, v.z);
    atomicAdd(gp + 3, v.w);
    if (t == 0) atomicAdd(&g_Z[c], zsh);
}

// ---------------------------------------------------------------------------
// Kernel C (merged topk + fusion + gather). UNCHANGED from R15.
// grid = NC + 32 + 256 = 296, block = 1024.
// ---------------------------------------------------------------------------
__global__ __launch_bounds__(1024) void topk_fusion_gather_kernel(
        const float* __restrict__ feats,
        const float* __restrict__ v_w,
        const float* __restrict__ v_b,
        float* __restrict__ out) {
    __shared__ __align__(16) float sg[NC * DIM];   // 32KB (fusion blocks)
    __shared__ unsigned warp_tot[32];
    __shared__ unsigned warp_off[32];
    __shared__ unsigned s_B, s_total;
    __shared__ unsigned long long cand[CANDMAX];

    int t = threadIdx.x;
    int warp = t >> 5, lane = t & 31;

    if (blockIdx.x >= NC + 32) {
        // ---------------- gather (256 blocks x 4 rows) ----------------
        int g = (int)blockIdx.x - (NC + 32);
        int row = g * 4 + (t >> 8);
        int c = row >> 7, k = row & 127;

        if (t == 0) {
            while (atomicAdd(&g_flag[c], 0u) == 0u)
                __nanosleep(64);
        }
        __syncthreads();
        __threadfence();

        int src = g_topidx[c][k];
        int ci = t & 255;
        const float4* s =
            (const float4*)(feats + ((size_t)c * NPER + src) * DIM);
        float4* dst = (float4*)(out + (size_t)row * DIM);
        dst[ci] = s[ci];
        return;
    }

    if (blockIdx.x >= NC) {
        // ---------------- fusion (32 blocks x 32 warps = 1024 rows) -------
        int rbase = (int)(blockIdx.x - NC) * 32;

        #pragma unroll
        for (int i = 0; i < 2; i++) {
            int idx = t + i * 1024;                 // float4 index [0,2048)
            int cc = idx >> 8;
            float invZ = 1.f / g_Z[cc];
            float4 gv = ((const float4*)(g_gvec[cc]))[idx & 255];
            gv.x *= invZ; gv.y *= invZ; gv.z *= invZ; gv.w *= invZ;
            ((float4*)sg)[idx] = gv;
        }
        __syncthreads();

        int o = rbase + warp;                       // my v_w row
        const float4* vr = (const float4*)(v_w + (size_t)o * DIM);
        float4 f[8];
        #pragma unroll
        for (int k = 0; k < 8; k++)
            f[k] = vr[lane + k * 32];
        float vb = v_b[o];

        #pragma unroll
        for (int cc = 0; cc < NC; cc++) {
            const float4* gr = (const float4*)(sg + cc * DIM);
            float d = 0.f;
            #pragma unroll
            for (int k = 0; k < 8; k++) {
                float4 g4 = gr[lane + k * 32];
                d += f[k].x * g4.x + f[k].y * g4.y
                   + f[k].z * g4.z + f[k].w * g4.w;
            }
            #pragma unroll
            for (int ofs = 16; ofs > 0; ofs >>= 1)
                d += __shfl_xor_sync(0xffffffffu, d, ofs);
            if (lane == 0)
                out[(size_t)1024 * 1024 + (size_t)cc * DIM + o] = d + vb;
        }
        return;
    }

    // ---------------- topk (8 blocks) ----------------
    int c = blockIdx.x;

    // ---- 1. histogram scan: find bin B where cumulative count >= 128 ----
    unsigned bins[4];
    {
        uint4 q = ((const uint4*)g_hist[c])[t];
        bins[0] = q.x; bins[1] = q.y; bins[2] = q.z; bins[3] = q.w;
    }
    unsigned loc = bins[0] + bins[1] + bins[2] + bins[3];

    unsigned incl = loc;
    #pragma unroll
    for (int o = 1; o < 32; o <<= 1) {
        unsigned u = __shfl_up_sync(0xffffffffu, incl, o);
        if (lane >= o) incl += u;
    }
    if (lane == 31) warp_tot[warp] = incl;
    __syncthreads();
    if (warp == 0) {
        unsigned v = warp_tot[lane];
        unsigned i2 = v;
        #pragma unroll
        for (int o = 1; o < 32; o <<= 1) {
            unsigned u = __shfl_up_sync(0xffffffffu, i2, o);
            if (lane >= o) i2 += u;
        }
        warp_off[lane] = i2 - v;   // exclusive per-warp offset
    }
    __syncthreads();

    unsigned texcl = warp_off[warp] + incl - loc;  // excl prefix before my bins
    if (texcl < TOPK && texcl + loc >= TOPK) {     // crossing in my 4 bins
        unsigned run = texcl;
        #pragma unroll
        for (int i = 0; i < 4; i++) {
            run += bins[i];
            if (run >= TOPK) { s_B = (unsigned)(t * 4 + i); s_total = run; break; }
        }
    }
    __syncthreads();
    unsigned B = s_B;

    // ---- 2. compact candidates (prefix <= B) via ballot-scan ----
    unsigned long long key[4];
    bool sel[4];
    unsigned laneoff[4];
    unsigned cnt_w = 0u;
    #pragma unroll
    for (int i = 0; i < 4; i++) {
        key[i] = g_keys[c][t + i * 1024];
        sel[i] = ((unsigned)(key[i] >> (64 - HBITS)) <= B);
        unsigned b = __ballot_sync(0xffffffffu, sel[i]);
        laneoff[i] = cnt_w + __popc(b & ((1u << lane) - 1u));
        cnt_w += __popc(b);
    }
    if (lane == 0) warp_tot[warp] = cnt_w;
    __syncthreads();
    if (warp == 0) {
        unsigned v = warp_tot[lane];
        unsigned i2 = v;
        #pragma unroll
        for (int o = 1; o < 32; o <<= 1) {
            unsigned u = __shfl_up_sync(0xffffffffu, i2, o);
            if (lane >= o) i2 += u;
        }
        warp_off[lane] = i2 - v;
    }
    __syncthreads();
    unsigned cbase = warp_off[warp];
    #pragma unroll
    for (int i = 0; i < 4; i++) {
        if (sel[i]) {
            unsigned p = cbase + laneoff[i];
            if (p < CANDMAX) cand[p] = key[i];
        }
    }
    __syncthreads();

    // ---- 3. rank-by-counting (candidate rank == global rank) ----
    unsigned cnt = s_total < CANDMAX ? s_total : CANDMAX;
    if (t < cnt) {
        unsigned long long mine = cand[t];
        unsigned rank = 0u;
        for (unsigned j = 0; j < cnt; j++)
            rank += (cand[j] < mine) ? 1u : 0u;
        if (rank < TOPK)
            g_topidx[c][rank] = (int)(unsigned)(mine & 0xffffffffu);
    }

    // ---- 4. release: publish topidx to gather blocks ----
    __syncthreads();
    __threadfence();
    if (t == 0) atomicExch(&g_flag[c], 1u);
}

// ---------------------------------------------------------------------------
extern "C" void kernel_launch(void* const* d_in, const int* in_sizes, int n_in,
                              void* d_out, int out_size) {
    const float* feats     = (const float*)d_in[0];  // [8,4096,1024]
    const float* key_feats = (const float*)d_in[1];  // [8,1,1024]
    const float* q_w       = (const float*)d_in[2];  // [128,1024]
    const float* q_b       = (const float*)d_in[3];  // [128]
    const float* v_w       = (const float*)d_in[4];  // [1024,1024]
    const float* v_b       = (const float*)d_in[5];  // [1024]
    float* out = (float*)d_out;  // selected [1024,1024] then fus [8,1024]

    prep_kernel<<<NC * 8, 256>>>(key_feats, q_w, q_b);   // <- profiled
    fused_pass_kernel<<<NC * 32, 256>>>(feats);
    topk_fusion_gather_kernel<<<NC + 32 + 256, 1024>>>(feats, v_w, v_b, out);
}

// round 17
// speedup vs baseline: 1.1577x; 1.1577x over previous
#include <cuda_runtime.h>
#include <math.h>

#define DIM   1024
#define NC    8
#define NPER  4096
#define QDIM  128
#define TOPK  128
#define HBITS 12
#define HBINS (1 << HBITS)      // 4096 bins per cluster
#define CANDMAX 640

// Scratch (no allocations allowed -> __device__ globals)
__device__ float g_qk[NC][QDIM];                 // q-projected key (incl. q_b)
__device__ float g_w[NC][DIM];                   // q_w^T @ qk per cluster
__device__ float g_b0[NC];                       // q_b . qk
__device__ unsigned long long g_keys[NC][NPER];  // (desc-map(score)<<32)|idx
__device__ unsigned g_hist[NC][HBINS];           // 12-bit key-prefix histogram
__device__ int   g_topidx[NC][TOPK];             // sorted top-k indices
__device__ float g_gvec[NC][DIM];                // sum_n e^{s_n} feats[n]
__device__ float g_Z[NC];                        // sum_n e^{s_n}
__device__ unsigned g_flag[NC];                  // topidx-ready flags

// ---------------------------------------------------------------------------
// Kernel A1: qk[c][q] = key[c] . q_w[q,:] + q_b[q]
// grid = NC*4 (32 q-rows per block), block = 256 (8 warps x 4 rows each).
// ---------------------------------------------------------------------------
__global__ __launch_bounds__(256) void qk_kernel(const float* __restrict__ key_feats,
                                                 const float* __restrict__ q_w,
                                                 const float* __restrict__ q_b) {
    int bid = blockIdx.x;
    int c = bid >> 2;
    int q0 = (bid & 3) * 32;
    int t = threadIdx.x, warp = t >> 5, lane = t & 31;

    // cache key row in registers: 8 float4/lane = full 1024 across the warp
    const float4* kr = (const float4*)(key_feats + (size_t)c * DIM);
    float4 kreg[8];
    #pragma unroll
    for (int k = 0; k < 8; k++) kreg[k] = kr[lane + k * 32];

    #pragma unroll
    for (int r = 0; r < 4; r++) {
        int q = q0 + warp * 4 + r;
        const float4* qr = (const float4*)(q_w + (size_t)q * DIM);
        float a = 0.f;
        #pragma unroll
        for (int k = 0; k < 8; k++) {
            float4 x = qr[lane + k * 32];
            a += x.x * kreg[k].x + x.y * kreg[k].y
               + x.z * kreg[k].z + x.w * kreg[k].w;
        }
        #pragma unroll
        for (int o = 16; o > 0; o >>= 1)
            a += __shfl_xor_sync(0xffffffffu, a, o);
        if (lane == 0) g_qk[c][q] = a + q_b[q];
    }
}

// ---------------------------------------------------------------------------
// Kernel A2: w[c][col] = sum_q qk[q] * q_w[q][col] ; b0 ; zero scratch.
// grid = NC*8 (128-col slice per block), block = 256.
// q-sum split across two thread halves (64 serial loads each, unroll 16).
// ---------------------------------------------------------------------------
__global__ __launch_bounds__(256) void w_kernel(const float* __restrict__ q_w,
                                                const float* __restrict__ q_b) {
    __shared__ __align__(16) float s_qk[QDIM];
    __shared__ float wred[128];
    __shared__ float bred[4];
    int bid = blockIdx.x;
    int c = bid >> 3, j = bid & 7;
    int t = threadIdx.x, warp = t >> 5, lane = t & 31;

    if (t < 128) {
        s_qk[t] = g_qk[c][t];
        ((uint4*)g_hist[c])[j * 128 + t] = make_uint4(0u, 0u, 0u, 0u);
        g_gvec[c][j * 128 + t] = 0.f;
    }
    if (j == 0 && t == 0) { g_Z[c] = 0.f; g_flag[c] = 0u; }
    __syncthreads();

    // w slice: col = j*128 + (t&127); q-range half chosen by t>>7
    int col = j * 128 + (t & 127);
    int q0 = (t >> 7) * 64;
    float wacc = 0.f;
    #pragma unroll 16
    for (int q = 0; q < 64; q++)
        wacc += s_qk[q0 + q] * q_w[(size_t)(q0 + q) * DIM + col];
    if (t >= 128) wred[t - 128] = wacc;
    __syncthreads();
    if (t < 128) g_w[c][col] = wacc + wred[t];

    // b0 = qk . q_b (block j==0 only)
    if (j == 0) {
        if (t < QDIM) {
            float p = s_qk[t] * q_b[t];
            #pragma unroll
            for (int o = 16; o > 0; o >>= 1)
                p += __shfl_xor_sync(0xffffffffu, p, o);
            if (lane == 0) bred[warp] = p;
        }
        __syncthreads();
        if (t == 0) g_b0[c] = bred[0] + bred[1] + bred[2] + bred[3];
    }
}

// ---------------------------------------------------------------------------
// Kernel B: single-wave fused pass (R15-validated, measured best). UNCHANGED.
// 256 blocks x 128 rows, warp owns 16 rows, 8 float4/lane per row.
// ---------------------------------------------------------------------------
__global__ __launch_bounds__(256) void fused_pass_kernel(const float* __restrict__ feats) {
    __shared__ __align__(16) float sw[DIM];
    __shared__ __align__(16) float sacc[DIM];
    __shared__ float zsh;

    int bid = blockIdx.x;
    int c = bid >> 5;                    // 32 blocks per cluster
    int base = (bid & 31) * 128;
    int t = threadIdx.x, warp = t >> 5, lane = t & 31;

    ((float4*)sw)[t] = ((const float4*)(g_w[c]))[t];
    ((float4*)sacc)[t] = make_float4(0.f, 0.f, 0.f, 0.f);
    if (t == 0) zsh = 0.f;
    float b0 = g_b0[c];
    __syncthreads();

    const float4* fb =
        (const float4*)(feats + ((size_t)c * NPER + base + (size_t)warp * 16) * DIM);

    float4 acc[8];
    #pragma unroll
    for (int k = 0; k < 8; k++) acc[k] = make_float4(0.f, 0.f, 0.f, 0.f);
    float zw = 0.f;

    for (int r = 0; r < 16; r++) {
        float4 f[8];
        #pragma unroll
        for (int k = 0; k < 8; k++)
            f[k] = fb[(size_t)r * 256 + lane + k * 32];

        float d = 0.f;
        #pragma unroll
        for (int k = 0; k < 8; k++) {
            float4 w4 = ((const float4*)sw)[lane + k * 32];
            d += f[k].x * w4.x + f[k].y * w4.y + f[k].z * w4.z + f[k].w * w4.w;
        }
        #pragma unroll
        for (int o = 16; o > 0; o >>= 1)
            d += __shfl_xor_sync(0xffffffffu, d, o);

        float s = (d + b0) * 0.08838834764831845f;  // 1/sqrt(128)
        float e = expf(s);                           // |s| small: safe
        zw += e;

        if (lane == 0) {
            int n = base + warp * 16 + r;
            unsigned u = __float_as_uint(s);
            u = (u & 0x80000000u) ? ~u : (u | 0x80000000u);  // ascending map
            unsigned dm = ~u;                                // descending map
            g_keys[c][n] = ((unsigned long long)dm << 32) | (unsigned)n;
            atomicAdd(&g_hist[c][dm >> (32 - HBITS)], 1u);   // spread bins
        }

        #pragma unroll
        for (int k = 0; k < 8; k++) {
            acc[k].x += e * f[k].x; acc[k].y += e * f[k].y;
            acc[k].z += e * f[k].z; acc[k].w += e * f[k].w;
        }
    }

    // cross-warp combine (serialized rounds)
    for (int wi = 0; wi < 8; wi++) {
        if (warp == wi) {
            #pragma unroll
            for (int k = 0; k < 8; k++) {
                float4* p = &((float4*)sacc)[lane + k * 32];
                float4 v = *p;
                v.x += acc[k].x; v.y += acc[k].y;
                v.z += acc[k].z; v.w += acc[k].w;
                *p = v;
            }
            if (lane == 0) zsh += zw;
        }
        __syncthreads();
    }

    float4 v = ((float4*)sacc)[t];
    float* gp = g_gvec[c] + t * 4;
    atomicAdd(gp + 0, v.x);
    atomicAdd(gp + 1, v.y);
    atomicAdd(gp + 2, v.z);
    atomicAdd(gp + 3, v.w);
    if (t == 0) atomicAdd(&g_Z[c], zsh);
}

// ---------------------------------------------------------------------------
// Kernel C (merged topk + fusion + gather). UNCHANGED from R15.
// grid = NC + 32 + 256 = 296, block = 1024.
// ---------------------------------------------------------------------------
__global__ __launch_bounds__(1024) void topk_fusion_gather_kernel(
        const float* __restrict__ feats,
        const float* __restrict__ v_w,
        const float* __restrict__ v_b,
        float* __restrict__ out) {
    __shared__ __align__(16) float sg[NC * DIM];   // 32KB (fusion blocks)
    __shared__ unsigned warp_tot[32];
    __shared__ unsigned warp_off[32];
    __shared__ unsigned s_B, s_total;
    __shared__ unsigned long long cand[CANDMAX];

    int t = threadIdx.x;
    int warp = t >> 5, lane = t & 31;

    if (blockIdx.x >= NC + 32) {
        // ---------------- gather (256 blocks x 4 rows) ----------------
        int g = (int)blockIdx.x - (NC + 32);
        int row = g * 4 + (t >> 8);
        int c = row >> 7, k = row & 127;

        if (t == 0) {
            while (atomicAdd(&g_flag[c], 0u) == 0u)
                __nanosleep(64);
        }
        __syncthreads();
        __threadfence();

        int src = g_topidx[c][k];
        int ci = t & 255;
        const float4* s =
            (const float4*)(feats + ((size_t)c * NPER + src) * DIM);
        float4* dst = (float4*)(out + (size_t)row * DIM);
        dst[ci] = s[ci];
        return;
    }

    if (blockIdx.x >= NC) {
        // ---------------- fusion (32 blocks x 32 warps = 1024 rows) -------
        int rbase = (int)(blockIdx.x - NC) * 32;

        #pragma unroll
        for (int i = 0; i < 2; i++) {
            int idx = t + i * 1024;                 // float4 index [0,2048)
            int cc = idx >> 8;
            float invZ = 1.f / g_Z[cc];
            float4 gv = ((const float4*)(g_gvec[cc]))[idx & 255];
            gv.x *= invZ; gv.y *= invZ; gv.z *= invZ; gv.w *= invZ;
            ((float4*)sg)[idx] = gv;
        }
        __syncthreads();

        int o = rbase + warp;                       // my v_w row
        const float4* vr = (const float4*)(v_w + (size_t)o * DIM);
        float4 f[8];
        #pragma unroll
        for (int k = 0; k < 8; k++)
            f[k] = vr[lane + k * 32];
        float vb = v_b[o];

        #pragma unroll
        for (int cc = 0; cc < NC; cc++) {
            const float4* gr = (const float4*)(sg + cc * DIM);
            float d = 0.f;
            #pragma unroll
            for (int k = 0; k < 8; k++) {
                float4 g4 = gr[lane + k * 32];
                d += f[k].x * g4.x + f[k].y * g4.y
                   + f[k].z * g4.z + f[k].w * g4.w;
            }
            #pragma unroll
            for (int ofs = 16; ofs > 0; ofs >>= 1)
                d += __shfl_xor_sync(0xffffffffu, d, ofs);
            if (lane == 0)
                out[(size_t)1024 * 1024 + (size_t)cc * DIM + o] = d + vb;
        }
        return;
    }

    // ---------------- topk (8 blocks) ----------------
    int c = blockIdx.x;

    // ---- 1. histogram scan: find bin B where cumulative count >= 128 ----
    unsigned bins[4];
    {
        uint4 q = ((const uint4*)g_hist[c])[t];
        bins[0] = q.x; bins[1] = q.y; bins[2] = q.z; bins[3] = q.w;
    }
    unsigned loc = bins[0] + bins[1] + bins[2] + bins[3];

    unsigned incl = loc;
    #pragma unroll
    for (int o = 1; o < 32; o <<= 1) {
        unsigned u = __shfl_up_sync(0xffffffffu, incl, o);
        if (lane >= o) incl += u;
    }
    if (lane == 31) warp_tot[warp] = incl;
    __syncthreads();
    if (warp == 0) {
        unsigned v = warp_tot[lane];
        unsigned i2 = v;
        #pragma unroll
        for (int o = 1; o < 32; o <<= 1) {
            unsigned u = __shfl_up_sync(0xffffffffu, i2, o);
            if (lane >= o) i2 += u;
        }
        warp_off[lane] = i2 - v;   // exclusive per-warp offset
    }
    __syncthreads();

    unsigned texcl = warp_off[warp] + incl - loc;  // excl prefix before my bins
    if (texcl < TOPK && texcl + loc >= TOPK) {     // crossing in my 4 bins
        unsigned run = texcl;
        #pragma unroll
        for (int i = 0; i < 4; i++) {
            run += bins[i];
            if (run >= TOPK) { s_B = (unsigned)(t * 4 + i); s_total = run; break; }
        }
    }
    __syncthreads();
    unsigned B = s_B;

    // ---- 2. compact candidates (prefix <= B) via ballot-scan ----
    unsigned long long key[4];
    bool sel[4];
    unsigned laneoff[4];
    unsigned cnt_w = 0u;
    #pragma unroll
    for (int i = 0; i < 4; i++) {
        key[i] = g_keys[c][t + i * 1024];
        sel[i] = ((unsigned)(key[i] >> (64 - HBITS)) <= B);
        unsigned b = __ballot_sync(0xffffffffu, sel[i]);
        laneoff[i] = cnt_w + __popc(b & ((1u << lane) - 1u));
        cnt_w += __popc(b);
    }
    if (lane == 0) warp_tot[warp] = cnt_w;
    __syncthreads();
    if (warp == 0) {
        unsigned v = warp_tot[lane];
        unsigned i2 = v;
        #pragma unroll
        for (int o = 1; o < 32; o <<= 1) {
            unsigned u = __shfl_up_sync(0xffffffffu, i2, o);
            if (lane >= o) i2 += u;
        }
        warp_off[lane] = i2 - v;
    }
    __syncthreads();
    unsigned cbase = warp_off[warp];
    #pragma unroll
    for (int i = 0; i < 4; i++) {
        if (sel[i]) {
            unsigned p = cbase + laneoff[i];
            if (p < CANDMAX) cand[p] = key[i];
        }
    }
    __syncthreads();

    // ---- 3. rank-by-counting (candidate rank == global rank) ----
    unsigned cnt = s_total < CANDMAX ? s_total : CANDMAX;
    if (t < cnt) {
        unsigned long long mine = cand[t];
        unsigned rank = 0u;
        for (unsigned j = 0; j < cnt; j++)
            rank += (cand[j] < mine) ? 1u : 0u;
        if (rank < TOPK)
            g_topidx[c][rank] = (int)(unsigned)(mine & 0xffffffffu);
    }

    // ---- 4. release: publish topidx to gather blocks ----
    __syncthreads();
    __threadfence();
    if (t == 0) atomicExch(&g_flag[c], 1u);
}

// ---------------------------------------------------------------------------
extern "C" void kernel_launch(void* const* d_in, const int* in_sizes, int n_in,
                              void* d_out, int out_size) {
    const float* feats     = (const float*)d_in[0];  // [8,4096,1024]
    const float* key_feats = (const float*)d_in[1];  // [8,1,1024]
    const float* q_w       = (const float*)d_in[2];  // [128,1024]
    const float* q_b       = (const float*)d_in[3];  // [128]
    const float* v_w       = (const float*)d_in[4];  // [1024,1024]
    const float* v_b       = (const float*)d_in[5];  // [1024]
    float* out = (float*)d_out;  // selected [1024,1024] then fus [8,1024]

    qk_kernel<<<NC * 4, 256>>>(key_feats, q_w, q_b);
    w_kernel<<<NC * 8, 256>>>(q_w, q_b);
    fused_pass_kernel<<<NC * 32, 256>>>(feats);
    topk_fusion_gather_kernel<<<NC + 32 + 256, 1024>>>(feats, v_w, v_b, out);
}